// round 12
// baseline (speedup 1.0000x reference)
#include <cuda_runtime.h>
#include <cstdint>

#define BSZ  4
#define NSEQ 2048
#define DIMC 1024
#define NH   16
#define DH   64
#define THREE_C 3072
#define NW (NSEQ / 64)     // mask words per row

typedef unsigned long long u64;

// ---------------- scratch (no allocs allowed) ----------------
__device__ float g_Q[BSZ * NH * DH * NSEQ];   // [b,h,d,n]  d-major (pre-scaled 1/8)
__device__ float g_K[BSZ * NH * DH * NSEQ];   // [b,h,d,n]  d-major
__device__ float g_V[BSZ * NH * NSEQ * DH];   // [b,h,n,d]
__device__ float g_O[BSZ * NSEQ * DIMC];      // [b,n,h*64+d]
__device__ u64   g_Mbits[BSZ * NSEQ * NW];    // bit=1 -> masked
__device__ int   g_mask_is_i32;

// ---------------- mask dtype probe ----------------
__global__ void detect_mask_kernel(const unsigned* __restrict__ m) {
    __shared__ int bad;
    if (threadIdx.x == 0) bad = 0;
    __syncthreads();
    for (int i = threadIdx.x; i < 4096; i += 256)
        if (m[i] > 1u) bad = 1;
    __syncthreads();
    if (threadIdx.x == 0) g_mask_is_i32 = bad ? 0 : 1;
}

// ---------------- mask bit-pack: one warp per row ----------------
__global__ __launch_bounds__(256) void pack_mask_kernel(const void* __restrict__ mask) {
    const int warp = (blockIdx.x * 256 + threadIdx.x) >> 5;   // row 0..8191
    const int lane = threadIdx.x & 31;
    const int mi32 = g_mask_is_i32;
    if (mi32) {
        const int* m = (const int*)mask + (size_t)warp * NSEQ;
#pragma unroll 4
        for (int w = 0; w < NW; w++) {
            unsigned b0 = __ballot_sync(0xffffffffu, m[w * 64 + lane] != 0);
            unsigned b1 = __ballot_sync(0xffffffffu, m[w * 64 + 32 + lane] != 0);
            if (lane == 0) g_Mbits[warp * NW + w] = (u64)b0 | ((u64)b1 << 32);
        }
    } else {
        const uint8_t* m = (const uint8_t*)mask + (size_t)warp * NSEQ;
#pragma unroll 4
        for (int w = 0; w < NW; w++) {
            unsigned b0 = __ballot_sync(0xffffffffu, m[w * 64 + lane] != 0);
            unsigned b1 = __ballot_sync(0xffffffffu, m[w * 64 + 32 + lane] != 0);
            if (lane == 0) g_Mbits[warp * NW + w] = (u64)b0 | ((u64)b1 << 32);
        }
    }
}

// ============ QKV GEMM (proven body; Q/K stored d-major) ============
__global__ __launch_bounds__(256, 2) void qkv_gemm_kernel(
    const float* __restrict__ X, const float* __restrict__ W, const float* __restrict__ bias)
{
    __shared__ float As[16][128];
    __shared__ float Bs[16][128];

    const int tid  = threadIdx.x;
    const int tx   = tid & 15, ty = tid >> 4;
    const int row0 = blockIdx.y * 128;
    const int col0 = blockIdx.x * 128;

    const int ra = tid >> 2;
    const int kc = (tid & 3) << 2;
    const int rb = tid >> 5;
    const int cb = (tid & 31) << 2;

    float acc[2][2][4][4];
#pragma unroll
    for (int ri = 0; ri < 2; ri++)
#pragma unroll
        for (int ci = 0; ci < 2; ci++)
#pragma unroll
            for (int i = 0; i < 4; i++)
#pragma unroll
                for (int j = 0; j < 4; j++) acc[ri][ci][i][j] = 0.f;

    float4 pa0 = *(const float4*)&X[(row0 + ra) * DIMC + kc];
    float4 pa1 = *(const float4*)&X[(row0 + ra + 64) * DIMC + kc];
    float4 pb0 = *(const float4*)&W[rb * THREE_C + col0 + cb];
    float4 pb1 = *(const float4*)&W[(rb + 8) * THREE_C + col0 + cb];

    for (int kt = 0; kt < 64; kt++) {
        As[kc + 0][ra] = pa0.x; As[kc + 1][ra] = pa0.y;
        As[kc + 2][ra] = pa0.z; As[kc + 3][ra] = pa0.w;
        As[kc + 0][ra + 64] = pa1.x; As[kc + 1][ra + 64] = pa1.y;
        As[kc + 2][ra + 64] = pa1.z; As[kc + 3][ra + 64] = pa1.w;
        *(float4*)&Bs[rb][cb]     = pb0;
        *(float4*)&Bs[rb + 8][cb] = pb1;
        __syncthreads();
        if (kt < 63) {
            const int k0 = (kt + 1) * 16;
            pa0 = *(const float4*)&X[(row0 + ra) * DIMC + k0 + kc];
            pa1 = *(const float4*)&X[(row0 + ra + 64) * DIMC + k0 + kc];
            pb0 = *(const float4*)&W[(k0 + rb) * THREE_C + col0 + cb];
            pb1 = *(const float4*)&W[(k0 + rb + 8) * THREE_C + col0 + cb];
        }
#pragma unroll
        for (int kk = 0; kk < 16; kk++) {
            float4 af0 = *(const float4*)&As[kk][ty * 4];
            float4 af1 = *(const float4*)&As[kk][64 + ty * 4];
            float4 bf0 = *(const float4*)&Bs[kk][tx * 4];
            float4 bf1 = *(const float4*)&Bs[kk][64 + tx * 4];
            float ar[2][4] = {{af0.x, af0.y, af0.z, af0.w}, {af1.x, af1.y, af1.z, af1.w}};
            float br[2][4] = {{bf0.x, bf0.y, bf0.z, bf0.w}, {bf1.x, bf1.y, bf1.z, bf1.w}};
#pragma unroll
            for (int ri = 0; ri < 2; ri++)
#pragma unroll
                for (int ci = 0; ci < 2; ci++)
#pragma unroll
                    for (int i = 0; i < 4; i++)
#pragma unroll
                        for (int j = 0; j < 4; j++)
                            acc[ri][ci][i][j] += ar[ri][i] * br[ci][j];
        }
        __syncthreads();
    }

#pragma unroll
    for (int ri = 0; ri < 2; ri++)
#pragma unroll
        for (int i = 0; i < 4; i++) {
            const int r  = row0 + ri * 64 + ty * 4 + i;
            const int bb = r >> 11;
            const int n  = r & 2047;
#pragma unroll
            for (int ci = 0; ci < 2; ci++) {
                const int c     = col0 + ci * 64 + tx * 4;
                const int three = c >> 10;
                const int rem   = c & 1023;
                const int h     = rem >> 6;
                const int d     = rem & 63;
                float4 bv = *(const float4*)&bias[c];
                float4 v;
                v.x = acc[ri][ci][i][0] + bv.x;
                v.y = acc[ri][ci][i][1] + bv.y;
                v.z = acc[ri][ci][i][2] + bv.z;
                v.w = acc[ri][ci][i][3] + bv.w;
                if (three == 2) {
                    *(float4*)&g_V[(((bb * NH + h) * NSEQ) + n) * DH + d] = v;
                } else {
                    float sc = 1.0f;
                    float* dst = g_K;
                    if (three == 0) { sc = 0.125f; dst = g_Q; }
                    const int base = ((bb * NH + h) * DH + d) * NSEQ + n;
                    dst[base]            = v.x * sc;
                    dst[base + NSEQ]     = v.y * sc;
                    dst[base + 2 * NSEQ] = v.z * sc;
                    dst[base + 3 * NSEQ] = v.w * sc;
                }
            }
        }
}

// ============ Flash attention: 256 thr, 4x8 micro, 16 warps/SM ============
// smem (floats): Qtd[64][128] @0, Kt[64][64] @8192, Vs[64][64] @12288, Ps[128][68] @16384
#define ATT_SMEM ((8192 + 4096 + 4096 + 128 * 68) * 4)   // 100352 B

__global__ __launch_bounds__(256, 2) void flash_attn_kernel()
{
    extern __shared__ float smf[];
    float* Qtd = smf;            // [64][128] d-major
    float* Kt  = smf + 8192;     // [64][64]  d-major
    float* Vs  = smf + 12288;    // [64][64]  key-major
    float* Ps  = smf + 16384;    // [128][68]

    const int b   = blockIdx.z;
    const int h   = blockIdx.y;
    const int q0  = blockIdx.x * 128;
    const int tid = threadIdx.x;
    const int tx  = tid & 7;     // key/col octet
    const int ty  = tid >> 3;    // row group (0..31), 4 rows each

    const int bh = b * NH + h;
    const float* __restrict__ Qg = g_Q + (size_t)bh * DH * NSEQ;
    const float* __restrict__ Kg = g_K + (size_t)bh * DH * NSEQ;
    const float* __restrict__ Vg = g_V + (size_t)bh * NSEQ * DH;
    const u64*   __restrict__ Mb = g_Mbits + ((size_t)b * NSEQ + q0) * NW;

    // Q tile load (coalesced, d-major, no transpose): 2048 float4 / 256 thr
#pragma unroll
    for (int it = 0; it < 8; it++) {
        const int idx = it * 256 + tid;
        const int d   = idx >> 5;
        const int r4  = (idx & 31) << 2;
        *(float4*)&Qtd[d * 128 + r4] = *(const float4*)&Qg[d * NSEQ + q0 + r4];
    }

    float lst[4], O[4][8];
#pragma unroll
    for (int i = 0; i < 4; i++) {
        lst[i] = 0.f;
#pragma unroll
        for (int c = 0; c < 8; c++) O[i][c] = 0.f;
    }

    for (int t = 0; t < NW; t++) {
        __syncthreads();   // previous tile's smem reads complete
        // load K/V tile straight to smem: 1024 float4 / 256 thr
#pragma unroll
        for (int it = 0; it < 4; it++) {
            const int idx = it * 256 + tid;
            const int r   = idx >> 4;
            const int c4  = (idx & 15) << 2;
            *(float4*)&Kt[r * 64 + c4] = *(const float4*)&Kg[r * NSEQ + t * 64 + c4];
            *(float4*)&Vs[r * 64 + c4] = *(const float4*)&Vg[(t * 64 + r) * DH + c4];
        }
        // mask words for this thread's 4 rows
        u64 wd[4];
#pragma unroll
        for (int i = 0; i < 4; i++)
            wd[i] = Mb[(ty * 4 + i) * NW + t];
        __syncthreads();   // tile ready (also covers Qtd on t=0)

        // ---- S = Q K^T ----
        float sacc[4][8];
#pragma unroll
        for (int i = 0; i < 4; i++)
#pragma unroll
            for (int j = 0; j < 8; j++) sacc[i][j] = 0.f;

#pragma unroll 4
        for (int d = 0; d < 64; d++) {
            float4 qa  = *(const float4*)&Qtd[d * 128 + ty * 4];
            float4 kb0 = *(const float4*)&Kt[d * 64 + tx * 8];
            float4 kb1 = *(const float4*)&Kt[d * 64 + tx * 8 + 4];
            float qv[4] = {qa.x, qa.y, qa.z, qa.w};
            float kv[8] = {kb0.x, kb0.y, kb0.z, kb0.w, kb1.x, kb1.y, kb1.z, kb1.w};
#pragma unroll
            for (int i = 0; i < 4; i++)
#pragma unroll
                for (int j = 0; j < 8; j++)
                    sacc[i][j] += qv[i] * kv[j];
        }

        // ---- un-shifted softmax numerators + write P ----
#pragma unroll
        for (int i = 0; i < 4; i++) {
            const unsigned mb = (unsigned)(wd[i] >> (tx * 8)) & 0xffu;
            float p[8], psum = 0.f;
#pragma unroll
            for (int j = 0; j < 8; j++) {
                p[j] = (mb & (1u << j)) ? 0.f : __expf(sacc[i][j]);
                psum += p[j];
            }
            lst[i] += psum;   // partial over tx lanes; reduced at end
            float4 pv0 = {p[0], p[1], p[2], p[3]};
            float4 pv1 = {p[4], p[5], p[6], p[7]};
            *(float4*)&Ps[(ty * 4 + i) * 68 + tx * 8]     = pv0;
            *(float4*)&Ps[(ty * 4 + i) * 68 + tx * 8 + 4] = pv1;
        }
        __syncwarp();   // P rows of this ty-group are warp-local (warp = 4 ty x 8 tx)

        // ---- O += P V ----
#pragma unroll 2
        for (int k4 = 0; k4 < 16; k4++) {
            float va[4][8];
#pragma unroll
            for (int k = 0; k < 4; k++) {
                float4 v0 = *(const float4*)&Vs[(k4 * 4 + k) * 64 + tx * 8];
                float4 v1 = *(const float4*)&Vs[(k4 * 4 + k) * 64 + tx * 8 + 4];
                va[k][0] = v0.x; va[k][1] = v0.y; va[k][2] = v0.z; va[k][3] = v0.w;
                va[k][4] = v1.x; va[k][5] = v1.y; va[k][6] = v1.z; va[k][7] = v1.w;
            }
#pragma unroll
            for (int i = 0; i < 4; i++) {
                float4 pf = *(const float4*)&Ps[(ty * 4 + i) * 68 + k4 * 4];
#pragma unroll
                for (int c = 0; c < 8; c++)
                    O[i][c] += pf.x * va[0][c] + pf.y * va[1][c]
                             + pf.z * va[2][c] + pf.w * va[3][c];
            }
        }
    }

    // final: reduce l over the 8 tx lanes, normalize, write out
#pragma unroll
    for (int i = 0; i < 4; i++) {
        float l = lst[i];
        l += __shfl_xor_sync(0xffffffffu, l, 1);
        l += __shfl_xor_sync(0xffffffffu, l, 2);
        l += __shfl_xor_sync(0xffffffffu, l, 4);
        const float inv = 1.0f / l;
        const int r = q0 + ty * 4 + i;
        float4 o0 = {O[i][0] * inv, O[i][1] * inv, O[i][2] * inv, O[i][3] * inv};
        float4 o1 = {O[i][4] * inv, O[i][5] * inv, O[i][6] * inv, O[i][7] * inv};
        float* op = &g_O[(size_t)(b * NSEQ + r) * DIMC + h * DH + tx * 8];
        *(float4*)op       = o0;
        *(float4*)(op + 4) = o1;
    }
}

// ============ Projection GEMM (proven body, unchanged) ============
__global__ __launch_bounds__(256, 2) void proj_gemm_kernel(
    const float* __restrict__ W, const float* __restrict__ bias, float* __restrict__ out)
{
    __shared__ float As[16][128];
    __shared__ float Bs[16][128];

    const int tid  = threadIdx.x;
    const int tx   = tid & 15, ty = tid >> 4;
    const int row0 = blockIdx.y * 128;
    const int col0 = blockIdx.x * 128;

    const int ra = tid >> 2;
    const int kc = (tid & 3) << 2;
    const int rb = tid >> 5;
    const int cb = (tid & 31) << 2;

    float acc[2][2][4][4];
#pragma unroll
    for (int ri = 0; ri < 2; ri++)
#pragma unroll
        for (int ci = 0; ci < 2; ci++)
#pragma unroll
            for (int i = 0; i < 4; i++)
#pragma unroll
                for (int j = 0; j < 4; j++) acc[ri][ci][i][j] = 0.f;

    float4 pa0 = *(const float4*)&g_O[(row0 + ra) * DIMC + kc];
    float4 pa1 = *(const float4*)&g_O[(row0 + ra + 64) * DIMC + kc];
    float4 pb0 = *(const float4*)&W[rb * DIMC + col0 + cb];
    float4 pb1 = *(const float4*)&W[(rb + 8) * DIMC + col0 + cb];

    for (int kt = 0; kt < 64; kt++) {
        As[kc + 0][ra] = pa0.x; As[kc + 1][ra] = pa0.y;
        As[kc + 2][ra] = pa0.z; As[kc + 3][ra] = pa0.w;
        As[kc + 0][ra + 64] = pa1.x; As[kc + 1][ra + 64] = pa1.y;
        As[kc + 2][ra + 64] = pa1.z; As[kc + 3][ra + 64] = pa1.w;
        *(float4*)&Bs[rb][cb]     = pb0;
        *(float4*)&Bs[rb + 8][cb] = pb1;
        __syncthreads();
        if (kt < 63) {
            const int k0 = (kt + 1) * 16;
            pa0 = *(const float4*)&g_O[(row0 + ra) * DIMC + k0 + kc];
            pa1 = *(const float4*)&g_O[(row0 + ra + 64) * DIMC + k0 + kc];
            pb0 = *(const float4*)&W[(k0 + rb) * DIMC + col0 + cb];
            pb1 = *(const float4*)&W[(k0 + rb + 8) * DIMC + col0 + cb];
        }
#pragma unroll
        for (int kk = 0; kk < 16; kk++) {
            float4 af0 = *(const float4*)&As[kk][ty * 4];
            float4 af1 = *(const float4*)&As[kk][64 + ty * 4];
            float4 bf0 = *(const float4*)&Bs[kk][tx * 4];
            float4 bf1 = *(const float4*)&Bs[kk][64 + tx * 4];
            float ar[2][4] = {{af0.x, af0.y, af0.z, af0.w}, {af1.x, af1.y, af1.z, af1.w}};
            float br[2][4] = {{bf0.x, bf0.y, bf0.z, bf0.w}, {bf1.x, bf1.y, bf1.z, bf1.w}};
#pragma unroll
            for (int ri = 0; ri < 2; ri++)
#pragma unroll
                for (int ci = 0; ci < 2; ci++)
#pragma unroll
                    for (int i = 0; i < 4; i++)
#pragma unroll
                        for (int j = 0; j < 4; j++)
                            acc[ri][ci][i][j] += ar[ri][i] * br[ci][j];
        }
        __syncthreads();
    }

#pragma unroll
    for (int ri = 0; ri < 2; ri++)
#pragma unroll
        for (int i = 0; i < 4; i++) {
            const int r = row0 + ri * 64 + ty * 4 + i;
#pragma unroll
            for (int ci = 0; ci < 2; ci++) {
                const int c = col0 + ci * 64 + tx * 4;
                float4 bv = *(const float4*)&bias[c];
                float4 v;
                v.x = acc[ri][ci][i][0] + bv.x;
                v.y = acc[ri][ci][i][1] + bv.y;
                v.z = acc[ri][ci][i][2] + bv.z;
                v.w = acc[ri][ci][i][3] + bv.w;
                *(float4*)&out[r * DIMC + c] = v;
            }
        }
}

// ---------------- launch ----------------
extern "C" void kernel_launch(void* const* d_in, const int* in_sizes, int n_in,
                              void* d_out, int out_size)
{
    const float* x     = (const float*)d_in[0];
    const void*  mask  = d_in[1];
    const float* Wqkv  = (const float*)d_in[2];
    const float* bqkv  = (const float*)d_in[3];
    const float* Wproj = (const float*)d_in[4];
    const float* bproj = (const float*)d_in[5];
    float* out = (float*)d_out;

    cudaFuncSetAttribute(flash_attn_kernel,
                         cudaFuncAttributeMaxDynamicSharedMemorySize, ATT_SMEM);

    detect_mask_kernel<<<1, 256>>>((const unsigned*)mask);
    pack_mask_kernel<<<(BSZ * NSEQ) / 8, 256>>>(mask);

    dim3 g1(THREE_C / 128, (BSZ * NSEQ) / 128);   // 24 x 64
    qkv_gemm_kernel<<<g1, 256>>>(x, Wqkv, bqkv);

    dim3 g2(NSEQ / 128, NH, BSZ);                 // 16 x 16 x 4
    flash_attn_kernel<<<g2, 256, ATT_SMEM>>>();

    dim3 g3(DIMC / 128, (BSZ * NSEQ) / 128);      // 8 x 64
    proj_gemm_kernel<<<g3, 256>>>(Wproj, bproj, out);
}

// round 13
// speedup vs baseline: 1.0233x; 1.0233x over previous
#include <cuda_runtime.h>
#include <cstdint>

#define BSZ  4
#define NSEQ 2048
#define DIMC 1024
#define NH   16
#define DH   64
#define THREE_C 3072
#define NW (NSEQ / 64)     // mask words per row

typedef unsigned long long u64;

// ---------------- scratch (no allocs allowed) ----------------
__device__ float g_Q[BSZ * NH * DH * NSEQ];   // [b,h,d,n]  d-major (pre-scaled 1/8)
__device__ float g_K[BSZ * NH * DH * NSEQ];   // [b,h,d,n]  d-major
__device__ float g_V[BSZ * NH * NSEQ * DH];   // [b,h,n,d]
__device__ float g_O[BSZ * NSEQ * DIMC];      // [b,n,h*64+d]
__device__ u64   g_Mbits[BSZ * NSEQ * NW];    // bit=1 -> masked
__device__ int   g_mask_is_i32;

// ---------------- mask dtype probe ----------------
__global__ void detect_mask_kernel(const unsigned* __restrict__ m) {
    __shared__ int bad;
    if (threadIdx.x == 0) bad = 0;
    __syncthreads();
    for (int i = threadIdx.x; i < 4096; i += 256)
        if (m[i] > 1u) bad = 1;
    __syncthreads();
    if (threadIdx.x == 0) g_mask_is_i32 = bad ? 0 : 1;
}

// ---------------- mask bit-pack: one warp per row ----------------
__global__ __launch_bounds__(256) void pack_mask_kernel(const void* __restrict__ mask) {
    const int warp = (blockIdx.x * 256 + threadIdx.x) >> 5;   // row 0..8191
    const int lane = threadIdx.x & 31;
    const int mi32 = g_mask_is_i32;
    if (mi32) {
        const int* m = (const int*)mask + (size_t)warp * NSEQ;
#pragma unroll 4
        for (int w = 0; w < NW; w++) {
            unsigned b0 = __ballot_sync(0xffffffffu, m[w * 64 + lane] != 0);
            unsigned b1 = __ballot_sync(0xffffffffu, m[w * 64 + 32 + lane] != 0);
            if (lane == 0) g_Mbits[warp * NW + w] = (u64)b0 | ((u64)b1 << 32);
        }
    } else {
        const uint8_t* m = (const uint8_t*)mask + (size_t)warp * NSEQ;
#pragma unroll 4
        for (int w = 0; w < NW; w++) {
            unsigned b0 = __ballot_sync(0xffffffffu, m[w * 64 + lane] != 0);
            unsigned b1 = __ballot_sync(0xffffffffu, m[w * 64 + 32 + lane] != 0);
            if (lane == 0) g_Mbits[warp * NW + w] = (u64)b0 | ((u64)b1 << 32);
        }
    }
}

// ============ QKV GEMM (proven body; Q/K stored d-major) ============
__global__ __launch_bounds__(256, 2) void qkv_gemm_kernel(
    const float* __restrict__ X, const float* __restrict__ W, const float* __restrict__ bias)
{
    __shared__ float As[16][128];
    __shared__ float Bs[16][128];

    const int tid  = threadIdx.x;
    const int tx   = tid & 15, ty = tid >> 4;
    const int row0 = blockIdx.y * 128;
    const int col0 = blockIdx.x * 128;

    const int ra = tid >> 2;
    const int kc = (tid & 3) << 2;
    const int rb = tid >> 5;
    const int cb = (tid & 31) << 2;

    float acc[2][2][4][4];
#pragma unroll
    for (int ri = 0; ri < 2; ri++)
#pragma unroll
        for (int ci = 0; ci < 2; ci++)
#pragma unroll
            for (int i = 0; i < 4; i++)
#pragma unroll
                for (int j = 0; j < 4; j++) acc[ri][ci][i][j] = 0.f;

    float4 pa0 = *(const float4*)&X[(row0 + ra) * DIMC + kc];
    float4 pa1 = *(const float4*)&X[(row0 + ra + 64) * DIMC + kc];
    float4 pb0 = *(const float4*)&W[rb * THREE_C + col0 + cb];
    float4 pb1 = *(const float4*)&W[(rb + 8) * THREE_C + col0 + cb];

    for (int kt = 0; kt < 64; kt++) {
        As[kc + 0][ra] = pa0.x; As[kc + 1][ra] = pa0.y;
        As[kc + 2][ra] = pa0.z; As[kc + 3][ra] = pa0.w;
        As[kc + 0][ra + 64] = pa1.x; As[kc + 1][ra + 64] = pa1.y;
        As[kc + 2][ra + 64] = pa1.z; As[kc + 3][ra + 64] = pa1.w;
        *(float4*)&Bs[rb][cb]     = pb0;
        *(float4*)&Bs[rb + 8][cb] = pb1;
        __syncthreads();
        if (kt < 63) {
            const int k0 = (kt + 1) * 16;
            pa0 = *(const float4*)&X[(row0 + ra) * DIMC + k0 + kc];
            pa1 = *(const float4*)&X[(row0 + ra + 64) * DIMC + k0 + kc];
            pb0 = *(const float4*)&W[(k0 + rb) * THREE_C + col0 + cb];
            pb1 = *(const float4*)&W[(k0 + rb + 8) * THREE_C + col0 + cb];
        }
#pragma unroll
        for (int kk = 0; kk < 16; kk++) {
            float4 af0 = *(const float4*)&As[kk][ty * 4];
            float4 af1 = *(const float4*)&As[kk][64 + ty * 4];
            float4 bf0 = *(const float4*)&Bs[kk][tx * 4];
            float4 bf1 = *(const float4*)&Bs[kk][64 + tx * 4];
            float ar[2][4] = {{af0.x, af0.y, af0.z, af0.w}, {af1.x, af1.y, af1.z, af1.w}};
            float br[2][4] = {{bf0.x, bf0.y, bf0.z, bf0.w}, {bf1.x, bf1.y, bf1.z, bf1.w}};
#pragma unroll
            for (int ri = 0; ri < 2; ri++)
#pragma unroll
                for (int ci = 0; ci < 2; ci++)
#pragma unroll
                    for (int i = 0; i < 4; i++)
#pragma unroll
                        for (int j = 0; j < 4; j++)
                            acc[ri][ci][i][j] += ar[ri][i] * br[ci][j];
        }
        __syncthreads();
    }

#pragma unroll
    for (int ri = 0; ri < 2; ri++)
#pragma unroll
        for (int i = 0; i < 4; i++) {
            const int r  = row0 + ri * 64 + ty * 4 + i;
            const int bb = r >> 11;
            const int n  = r & 2047;
#pragma unroll
            for (int ci = 0; ci < 2; ci++) {
                const int c     = col0 + ci * 64 + tx * 4;
                const int three = c >> 10;
                const int rem   = c & 1023;
                const int h     = rem >> 6;
                const int d     = rem & 63;
                float4 bv = *(const float4*)&bias[c];
                float4 v;
                v.x = acc[ri][ci][i][0] + bv.x;
                v.y = acc[ri][ci][i][1] + bv.y;
                v.z = acc[ri][ci][i][2] + bv.z;
                v.w = acc[ri][ci][i][3] + bv.w;
                if (three == 2) {
                    *(float4*)&g_V[(((bb * NH + h) * NSEQ) + n) * DH + d] = v;
                } else {
                    float sc = 1.0f;
                    float* dst = g_K;
                    if (three == 0) { sc = 0.125f; dst = g_Q; }
                    const int base = ((bb * NH + h) * DH + d) * NSEQ + n;
                    dst[base]            = v.x * sc;
                    dst[base + NSEQ]     = v.y * sc;
                    dst[base + 2 * NSEQ] = v.z * sc;
                    dst[base + 3 * NSEQ] = v.w * sc;
                }
            }
        }
}

// ============ Flash attention: 64q x 64k tiles, 2048 CTAs, 128 thr, 4x8 micro ============
// smem (floats): Qtd[64][64] @0, Kt[64][64] @4096, Vs[64][64] @8192, Ps[64][68] @12288
// Padded to 76KB to pin exactly 2 CTAs/SM (predictable wave count).
#define ATT_SMEM (76 * 1024)

__global__ __launch_bounds__(128, 2) void flash_attn_kernel()
{
    extern __shared__ float smf[];
    float* Qtd = smf;            // [64 d][64 r]
    float* Kt  = smf + 4096;     // [64 d][64 k]
    float* Vs  = smf + 8192;     // [64 k][64 c]
    float* Ps  = smf + 12288;    // [64 r][68]

    const int b   = blockIdx.z;
    const int h   = blockIdx.y;
    const int q0  = blockIdx.x * 64;
    const int tid = threadIdx.x;
    const int tx  = tid & 7;     // key/col octet
    const int ty  = tid >> 3;    // row group (0..15), 4 rows each

    const int bh = b * NH + h;
    const float* __restrict__ Qg = g_Q + (size_t)bh * DH * NSEQ;
    const float* __restrict__ Kg = g_K + (size_t)bh * DH * NSEQ;
    const float* __restrict__ Vg = g_V + (size_t)bh * NSEQ * DH;
    const u64*   __restrict__ Mb = g_Mbits + ((size_t)b * NSEQ + q0) * NW;

    // Q tile load (coalesced, d-major): 1024 float4 / 128 thr
#pragma unroll
    for (int it = 0; it < 8; it++) {
        const int idx = it * 128 + tid;
        const int d   = idx >> 4;
        const int r4  = (idx & 15) << 2;
        *(float4*)&Qtd[d * 64 + r4] = *(const float4*)&Qg[d * NSEQ + q0 + r4];
    }

    float lst[4], O[4][8];
#pragma unroll
    for (int i = 0; i < 4; i++) {
        lst[i] = 0.f;
#pragma unroll
        for (int c = 0; c < 8; c++) O[i][c] = 0.f;
    }

    // preload tile 0 K/V into registers
    float4 rK[8], rV[8];
#pragma unroll
    for (int it = 0; it < 8; it++) {
        const int idx = it * 128 + tid;   // 0..1023 float4
        const int r   = idx >> 4;
        const int c4  = (idx & 15) << 2;
        rK[it] = *(const float4*)&Kg[r * NSEQ + c4];
        rV[it] = *(const float4*)&Vg[r * DH + c4];
    }

    for (int t = 0; t < NW; t++) {
        __syncthreads();   // previous tile's smem reads complete
        // store prefetched K/V tile
#pragma unroll
        for (int it = 0; it < 8; it++) {
            const int idx = it * 128 + tid;
            const int r   = idx >> 4;
            const int c4  = (idx & 15) << 2;
            *(float4*)&Kt[r * 64 + c4] = rK[it];
            *(float4*)&Vs[r * 64 + c4] = rV[it];
        }
        // mask words for this thread's 4 rows
        u64 wd[4];
#pragma unroll
        for (int i = 0; i < 4; i++)
            wd[i] = Mb[(ty * 4 + i) * NW + t];
        __syncthreads();   // tile ready (also covers Qtd on t=0)

        // ---- S = Q K^T ----
        float sacc[4][8];
#pragma unroll
        for (int i = 0; i < 4; i++)
#pragma unroll
            for (int j = 0; j < 8; j++) sacc[i][j] = 0.f;

#pragma unroll 4
        for (int d = 0; d < 64; d++) {
            float4 qa  = *(const float4*)&Qtd[d * 64 + ty * 4];
            float4 kb0 = *(const float4*)&Kt[d * 64 + tx * 8];
            float4 kb1 = *(const float4*)&Kt[d * 64 + tx * 8 + 4];
            float qv[4] = {qa.x, qa.y, qa.z, qa.w};
            float kv[8] = {kb0.x, kb0.y, kb0.z, kb0.w, kb1.x, kb1.y, kb1.z, kb1.w};
#pragma unroll
            for (int i = 0; i < 4; i++)
#pragma unroll
                for (int j = 0; j < 8; j++)
                    sacc[i][j] += qv[i] * kv[j];
        }

        // prefetch next tile's K/V (hidden under softmax + PV)
        if (t < NW - 1) {
            const int kt1 = (t + 1) * 64;
#pragma unroll
            for (int it = 0; it < 8; it++) {
                const int idx = it * 128 + tid;
                const int r   = idx >> 4;
                const int c4  = (idx & 15) << 2;
                rK[it] = *(const float4*)&Kg[r * NSEQ + kt1 + c4];
                rV[it] = *(const float4*)&Vg[(kt1 + r) * DH + c4];
            }
        }

        // ---- un-shifted softmax numerators + write P ----
#pragma unroll
        for (int i = 0; i < 4; i++) {
            const unsigned mb = (unsigned)(wd[i] >> (tx * 8)) & 0xffu;
            float p[8], psum = 0.f;
#pragma unroll
            for (int j = 0; j < 8; j++) {
                p[j] = (mb & (1u << j)) ? 0.f : __expf(sacc[i][j]);
                psum += p[j];
            }
            lst[i] += psum;   // partial over tx lanes; reduced at end
            float4 pv0 = {p[0], p[1], p[2], p[3]};
            float4 pv1 = {p[4], p[5], p[6], p[7]};
            *(float4*)&Ps[(ty * 4 + i) * 68 + tx * 8]     = pv0;
            *(float4*)&Ps[(ty * 4 + i) * 68 + tx * 8 + 4] = pv1;
        }
        __syncwarp();   // P rows of this warp (rows 16w..16w+15) are warp-local

        // ---- O += P V ----
#pragma unroll 2
        for (int k4 = 0; k4 < 16; k4++) {
            float va[4][8];
#pragma unroll
            for (int k = 0; k < 4; k++) {
                float4 v0 = *(const float4*)&Vs[(k4 * 4 + k) * 64 + tx * 8];
                float4 v1 = *(const float4*)&Vs[(k4 * 4 + k) * 64 + tx * 8 + 4];
                va[k][0] = v0.x; va[k][1] = v0.y; va[k][2] = v0.z; va[k][3] = v0.w;
                va[k][4] = v1.x; va[k][5] = v1.y; va[k][6] = v1.z; va[k][7] = v1.w;
            }
#pragma unroll
            for (int i = 0; i < 4; i++) {
                float4 pf = *(const float4*)&Ps[(ty * 4 + i) * 68 + k4 * 4];
#pragma unroll
                for (int c = 0; c < 8; c++)
                    O[i][c] += pf.x * va[0][c] + pf.y * va[1][c]
                             + pf.z * va[2][c] + pf.w * va[3][c];
            }
        }
    }

    // final: reduce l over the 8 tx lanes, normalize, write out
#pragma unroll
    for (int i = 0; i < 4; i++) {
        float l = lst[i];
        l += __shfl_xor_sync(0xffffffffu, l, 1);
        l += __shfl_xor_sync(0xffffffffu, l, 2);
        l += __shfl_xor_sync(0xffffffffu, l, 4);
        const float inv = 1.0f / l;
        const int r = q0 + ty * 4 + i;
        float4 o0 = {O[i][0] * inv, O[i][1] * inv, O[i][2] * inv, O[i][3] * inv};
        float4 o1 = {O[i][4] * inv, O[i][5] * inv, O[i][6] * inv, O[i][7] * inv};
        float* op = &g_O[(size_t)(b * NSEQ + r) * DIMC + h * DH + tx * 8];
        *(float4*)op       = o0;
        *(float4*)(op + 4) = o1;
    }
}

// ============ Projection GEMM (proven body, unchanged) ============
__global__ __launch_bounds__(256, 2) void proj_gemm_kernel(
    const float* __restrict__ W, const float* __restrict__ bias, float* __restrict__ out)
{
    __shared__ float As[16][128];
    __shared__ float Bs[16][128];

    const int tid  = threadIdx.x;
    const int tx   = tid & 15, ty = tid >> 4;
    const int row0 = blockIdx.y * 128;
    const int col0 = blockIdx.x * 128;

    const int ra = tid >> 2;
    const int kc = (tid & 3) << 2;
    const int rb = tid >> 5;
    const int cb = (tid & 31) << 2;

    float acc[2][2][4][4];
#pragma unroll
    for (int ri = 0; ri < 2; ri++)
#pragma unroll
        for (int ci = 0; ci < 2; ci++)
#pragma unroll
            for (int i = 0; i < 4; i++)
#pragma unroll
                for (int j = 0; j < 4; j++) acc[ri][ci][i][j] = 0.f;

    float4 pa0 = *(const float4*)&g_O[(row0 + ra) * DIMC + kc];
    float4 pa1 = *(const float4*)&g_O[(row0 + ra + 64) * DIMC + kc];
    float4 pb0 = *(const float4*)&W[rb * DIMC + col0 + cb];
    float4 pb1 = *(const float4*)&W[(rb + 8) * DIMC + col0 + cb];

    for (int kt = 0; kt < 64; kt++) {
        As[kc + 0][ra] = pa0.x; As[kc + 1][ra] = pa0.y;
        As[kc + 2][ra] = pa0.z; As[kc + 3][ra] = pa0.w;
        As[kc + 0][ra + 64] = pa1.x; As[kc + 1][ra + 64] = pa1.y;
        As[kc + 2][ra + 64] = pa1.z; As[kc + 3][ra + 64] = pa1.w;
        *(float4*)&Bs[rb][cb]     = pb0;
        *(float4*)&Bs[rb + 8][cb] = pb1;
        __syncthreads();
        if (kt < 63) {
            const int k0 = (kt + 1) * 16;
            pa0 = *(const float4*)&g_O[(row0 + ra) * DIMC + k0 + kc];
            pa1 = *(const float4*)&g_O[(row0 + ra + 64) * DIMC + k0 + kc];
            pb0 = *(const float4*)&W[(k0 + rb) * DIMC + col0 + cb];
            pb1 = *(const float4*)&W[(k0 + rb + 8) * DIMC + col0 + cb];
        }
#pragma unroll
        for (int kk = 0; kk < 16; kk++) {
            float4 af0 = *(const float4*)&As[kk][ty * 4];
            float4 af1 = *(const float4*)&As[kk][64 + ty * 4];
            float4 bf0 = *(const float4*)&Bs[kk][tx * 4];
            float4 bf1 = *(const float4*)&Bs[kk][64 + tx * 4];
            float ar[2][4] = {{af0.x, af0.y, af0.z, af0.w}, {af1.x, af1.y, af1.z, af1.w}};
            float br[2][4] = {{bf0.x, bf0.y, bf0.z, bf0.w}, {bf1.x, bf1.y, bf1.z, bf1.w}};
#pragma unroll
            for (int ri = 0; ri < 2; ri++)
#pragma unroll
                for (int ci = 0; ci < 2; ci++)
#pragma unroll
                    for (int i = 0; i < 4; i++)
#pragma unroll
                        for (int j = 0; j < 4; j++)
                            acc[ri][ci][i][j] += ar[ri][i] * br[ci][j];
        }
        __syncthreads();
    }

#pragma unroll
    for (int ri = 0; ri < 2; ri++)
#pragma unroll
        for (int i = 0; i < 4; i++) {
            const int r = row0 + ri * 64 + ty * 4 + i;
#pragma unroll
            for (int ci = 0; ci < 2; ci++) {
                const int c = col0 + ci * 64 + tx * 4;
                float4 bv = *(const float4*)&bias[c];
                float4 v;
                v.x = acc[ri][ci][i][0] + bv.x;
                v.y = acc[ri][ci][i][1] + bv.y;
                v.z = acc[ri][ci][i][2] + bv.z;
                v.w = acc[ri][ci][i][3] + bv.w;
                *(float4*)&out[r * DIMC + c] = v;
            }
        }
}

// ---------------- launch ----------------
extern "C" void kernel_launch(void* const* d_in, const int* in_sizes, int n_in,
                              void* d_out, int out_size)
{
    const float* x     = (const float*)d_in[0];
    const void*  mask  = d_in[1];
    const float* Wqkv  = (const float*)d_in[2];
    const float* bqkv  = (const float*)d_in[3];
    const float* Wproj = (const float*)d_in[4];
    const float* bproj = (const float*)d_in[5];
    float* out = (float*)d_out;

    cudaFuncSetAttribute(flash_attn_kernel,
                         cudaFuncAttributeMaxDynamicSharedMemorySize, ATT_SMEM);

    detect_mask_kernel<<<1, 256>>>((const unsigned*)mask);
    pack_mask_kernel<<<(BSZ * NSEQ) / 8, 256>>>(mask);

    dim3 g1(THREE_C / 128, (BSZ * NSEQ) / 128);   // 24 x 64
    qkv_gemm_kernel<<<g1, 256>>>(x, Wqkv, bqkv);

    dim3 g2(NSEQ / 64, NH, BSZ);                  // 32 x 16 x 4 = 2048 CTAs
    flash_attn_kernel<<<g2, 128, ATT_SMEM>>>();

    dim3 g3(DIMC / 128, (BSZ * NSEQ) / 128);      // 8 x 64
    proj_gemm_kernel<<<g3, 256>>>(Wproj, bproj, out);
}

// round 14
// speedup vs baseline: 1.0786x; 1.0541x over previous
#include <cuda_runtime.h>
#include <cstdint>

#define BSZ  4
#define NSEQ 2048
#define DIMC 1024
#define NH   16
#define DH   64
#define THREE_C 3072
#define NW (NSEQ / 64)     // mask words per row

typedef unsigned long long u64;

// ---------------- scratch (no allocs allowed) ----------------
__device__ float g_Q[BSZ * NH * DH * NSEQ];   // [b,h,d,n]  d-major (pre-scaled log2e/8)
__device__ float g_K[BSZ * NH * DH * NSEQ];   // [b,h,d,n]  d-major
__device__ float g_V[BSZ * NH * NSEQ * DH];   // [b,h,n,d]
__device__ float g_O[BSZ * NSEQ * DIMC];      // [b,n,h*64+d]
__device__ u64   g_Mbits[BSZ * NSEQ * NW];    // bit=1 -> masked
__device__ int   g_mask_is_i32;

__device__ __forceinline__ float fast_ex2(float x) {
    float r; asm("ex2.approx.f32 %0, %1;" : "=f"(r) : "f"(x)); return r;
}

// ---------------- mask dtype probe ----------------
__global__ void detect_mask_kernel(const unsigned* __restrict__ m) {
    __shared__ int bad;
    if (threadIdx.x == 0) bad = 0;
    __syncthreads();
    for (int i = threadIdx.x; i < 4096; i += 256)
        if (m[i] > 1u) bad = 1;
    __syncthreads();
    if (threadIdx.x == 0) g_mask_is_i32 = bad ? 0 : 1;
}

// ---------------- mask bit-pack: one warp per row ----------------
__global__ __launch_bounds__(256) void pack_mask_kernel(const void* __restrict__ mask) {
    const int warp = (blockIdx.x * 256 + threadIdx.x) >> 5;   // row 0..8191
    const int lane = threadIdx.x & 31;
    const int mi32 = g_mask_is_i32;
    if (mi32) {
        const int* m = (const int*)mask + (size_t)warp * NSEQ;
#pragma unroll 4
        for (int w = 0; w < NW; w++) {
            unsigned b0 = __ballot_sync(0xffffffffu, m[w * 64 + lane] != 0);
            unsigned b1 = __ballot_sync(0xffffffffu, m[w * 64 + 32 + lane] != 0);
            if (lane == 0) g_Mbits[warp * NW + w] = (u64)b0 | ((u64)b1 << 32);
        }
    } else {
        const uint8_t* m = (const uint8_t*)mask + (size_t)warp * NSEQ;
#pragma unroll 4
        for (int w = 0; w < NW; w++) {
            unsigned b0 = __ballot_sync(0xffffffffu, m[w * 64 + lane] != 0);
            unsigned b1 = __ballot_sync(0xffffffffu, m[w * 64 + 32 + lane] != 0);
            if (lane == 0) g_Mbits[warp * NW + w] = (u64)b0 | ((u64)b1 << 32);
        }
    }
}

// ============ QKV GEMM (proven body; Q/K d-major; Q scaled by log2e/8) ============
__global__ __launch_bounds__(256, 2) void qkv_gemm_kernel(
    const float* __restrict__ X, const float* __restrict__ W, const float* __restrict__ bias)
{
    __shared__ float As[16][128];
    __shared__ float Bs[16][128];

    const int tid  = threadIdx.x;
    const int tx   = tid & 15, ty = tid >> 4;
    const int row0 = blockIdx.y * 128;
    const int col0 = blockIdx.x * 128;

    const int ra = tid >> 2;
    const int kc = (tid & 3) << 2;
    const int rb = tid >> 5;
    const int cb = (tid & 31) << 2;

    float acc[2][2][4][4];
#pragma unroll
    for (int ri = 0; ri < 2; ri++)
#pragma unroll
        for (int ci = 0; ci < 2; ci++)
#pragma unroll
            for (int i = 0; i < 4; i++)
#pragma unroll
                for (int j = 0; j < 4; j++) acc[ri][ci][i][j] = 0.f;

    float4 pa0 = *(const float4*)&X[(row0 + ra) * DIMC + kc];
    float4 pa1 = *(const float4*)&X[(row0 + ra + 64) * DIMC + kc];
    float4 pb0 = *(const float4*)&W[rb * THREE_C + col0 + cb];
    float4 pb1 = *(const float4*)&W[(rb + 8) * THREE_C + col0 + cb];

    for (int kt = 0; kt < 64; kt++) {
        As[kc + 0][ra] = pa0.x; As[kc + 1][ra] = pa0.y;
        As[kc + 2][ra] = pa0.z; As[kc + 3][ra] = pa0.w;
        As[kc + 0][ra + 64] = pa1.x; As[kc + 1][ra + 64] = pa1.y;
        As[kc + 2][ra + 64] = pa1.z; As[kc + 3][ra + 64] = pa1.w;
        *(float4*)&Bs[rb][cb]     = pb0;
        *(float4*)&Bs[rb + 8][cb] = pb1;
        __syncthreads();
        if (kt < 63) {
            const int k0 = (kt + 1) * 16;
            pa0 = *(const float4*)&X[(row0 + ra) * DIMC + k0 + kc];
            pa1 = *(const float4*)&X[(row0 + ra + 64) * DIMC + k0 + kc];
            pb0 = *(const float4*)&W[(k0 + rb) * THREE_C + col0 + cb];
            pb1 = *(const float4*)&W[(k0 + rb + 8) * THREE_C + col0 + cb];
        }
#pragma unroll
        for (int kk = 0; kk < 16; kk++) {
            float4 af0 = *(const float4*)&As[kk][ty * 4];
            float4 af1 = *(const float4*)&As[kk][64 + ty * 4];
            float4 bf0 = *(const float4*)&Bs[kk][tx * 4];
            float4 bf1 = *(const float4*)&Bs[kk][64 + tx * 4];
            float ar[2][4] = {{af0.x, af0.y, af0.z, af0.w}, {af1.x, af1.y, af1.z, af1.w}};
            float br[2][4] = {{bf0.x, bf0.y, bf0.z, bf0.w}, {bf1.x, bf1.y, bf1.z, bf1.w}};
#pragma unroll
            for (int ri = 0; ri < 2; ri++)
#pragma unroll
                for (int ci = 0; ci < 2; ci++)
#pragma unroll
                    for (int i = 0; i < 4; i++)
#pragma unroll
                        for (int j = 0; j < 4; j++)
                            acc[ri][ci][i][j] += ar[ri][i] * br[ci][j];
        }
        __syncthreads();
    }

    // Q scale folds softmax's log2(e): exp(qk/8) == exp2((log2e/8 * q) . k)
    const float QSCALE = 0.18033688011f;   // 1.4426950408f / 8
#pragma unroll
    for (int ri = 0; ri < 2; ri++)
#pragma unroll
        for (int i = 0; i < 4; i++) {
            const int r  = row0 + ri * 64 + ty * 4 + i;
            const int bb = r >> 11;
            const int n  = r & 2047;
#pragma unroll
            for (int ci = 0; ci < 2; ci++) {
                const int c     = col0 + ci * 64 + tx * 4;
                const int three = c >> 10;
                const int rem   = c & 1023;
                const int h     = rem >> 6;
                const int d     = rem & 63;
                float4 bv = *(const float4*)&bias[c];
                float4 v;
                v.x = acc[ri][ci][i][0] + bv.x;
                v.y = acc[ri][ci][i][1] + bv.y;
                v.z = acc[ri][ci][i][2] + bv.z;
                v.w = acc[ri][ci][i][3] + bv.w;
                if (three == 2) {
                    *(float4*)&g_V[(((bb * NH + h) * NSEQ) + n) * DH + d] = v;
                } else {
                    float sc = 1.0f;
                    float* dst = g_K;
                    if (three == 0) { sc = QSCALE; dst = g_Q; }
                    const int base = ((bb * NH + h) * DH + d) * NSEQ + n;
                    dst[base]            = v.x * sc;
                    dst[base + NSEQ]     = v.y * sc;
                    dst[base + 2 * NSEQ] = v.z * sc;
                    dst[base + 3 * NSEQ] = v.w * sc;
                }
            }
        }
}

// ============ Flash attention: 128 thr, 8x8 micro, prefetch, un-shifted exp2 ============
// smem (floats): Qtd[64][128] @0, Kt[64][64] @8192, Vs[64][64] @12288, Ps[128][68] @16384
#define ATT_SMEM ((8192 + 4096 + 4096 + 128 * 68) * 4)   // 100352 B

__global__ __launch_bounds__(128, 2) void flash_attn_kernel()
{
    extern __shared__ float smf[];
    float* Qtd = smf;            // [64 d][128 r]
    float* Kt  = smf + 8192;     // [64 d][64 k]
    float* Vs  = smf + 12288;    // [64 k][64 c]
    float* Ps  = smf + 16384;    // [128 r][68]

    const int b   = blockIdx.z;
    const int h   = blockIdx.y;
    const int q0  = blockIdx.x * 128;
    const int tid = threadIdx.x;
    const int tx  = tid & 7;     // key/col octet
    const int ty  = tid >> 3;    // row group (0..15), 8 rows each

    const int bh = b * NH + h;
    const float* __restrict__ Qg = g_Q + (size_t)bh * DH * NSEQ;
    const float* __restrict__ Kg = g_K + (size_t)bh * DH * NSEQ;
    const float* __restrict__ Vg = g_V + (size_t)bh * NSEQ * DH;
    const u64*   __restrict__ Mb = g_Mbits + ((size_t)b * NSEQ + q0) * NW;

    // Q tile load (coalesced, d-major, no transpose): 2048 float4 / 128 thr
#pragma unroll
    for (int it = 0; it < 16; it++) {
        const int idx = it * 128 + tid;
        const int d   = idx >> 5;
        const int r4  = (idx & 31) << 2;
        *(float4*)&Qtd[d * 128 + r4] = *(const float4*)&Qg[d * NSEQ + q0 + r4];
    }

    float lst[8], O[8][8];
#pragma unroll
    for (int i = 0; i < 8; i++) {
        lst[i] = 0.f;
#pragma unroll
        for (int c = 0; c < 8; c++) O[i][c] = 0.f;
    }

    // preload tile 0 K/V into registers
    float4 rK[8], rV[8];
#pragma unroll
    for (int it = 0; it < 8; it++) {
        const int idx = it * 128 + tid;   // 0..1023 float4
        const int r   = idx >> 4;
        const int c4  = (idx & 15) << 2;
        rK[it] = *(const float4*)&Kg[r * NSEQ + c4];
        rV[it] = *(const float4*)&Vg[r * DH + c4];
    }

    for (int t = 0; t < NW; t++) {
        __syncthreads();   // previous tile's smem reads complete
        // store prefetched K/V tile
#pragma unroll
        for (int it = 0; it < 8; it++) {
            const int idx = it * 128 + tid;
            const int r   = idx >> 4;
            const int c4  = (idx & 15) << 2;
            *(float4*)&Kt[r * 64 + c4] = rK[it];
            *(float4*)&Vs[r * 64 + c4] = rV[it];
        }
        // mask words for this thread's 8 rows
        u64 wd[8];
#pragma unroll
        for (int i = 0; i < 8; i++)
            wd[i] = Mb[(ty * 8 + i) * NW + t];
        __syncthreads();   // tile ready (also covers Qtd on t=0)

        // ---- S = Q K^T ----
        float sacc[8][8];
#pragma unroll
        for (int i = 0; i < 8; i++)
#pragma unroll
            for (int j = 0; j < 8; j++) sacc[i][j] = 0.f;

#pragma unroll 2
        for (int d = 0; d < 64; d++) {
            float4 qa0 = *(const float4*)&Qtd[d * 128 + ty * 8];
            float4 qa1 = *(const float4*)&Qtd[d * 128 + ty * 8 + 4];
            float4 kb0 = *(const float4*)&Kt[d * 64 + tx * 8];
            float4 kb1 = *(const float4*)&Kt[d * 64 + tx * 8 + 4];
            float qa[8] = {qa0.x, qa0.y, qa0.z, qa0.w, qa1.x, qa1.y, qa1.z, qa1.w};
            float kb[8] = {kb0.x, kb0.y, kb0.z, kb0.w, kb1.x, kb1.y, kb1.z, kb1.w};
#pragma unroll
            for (int i = 0; i < 8; i++)
#pragma unroll
                for (int j = 0; j < 8; j++)
                    sacc[i][j] += qa[i] * kb[j];
        }

        // prefetch next tile's K/V (hidden under softmax + PV)
        if (t < NW - 1) {
            const int kt1 = (t + 1) * 64;
#pragma unroll
            for (int it = 0; it < 8; it++) {
                const int idx = it * 128 + tid;
                const int r   = idx >> 4;
                const int c4  = (idx & 15) << 2;
                rK[it] = *(const float4*)&Kg[r * NSEQ + kt1 + c4];
                rV[it] = *(const float4*)&Vg[(kt1 + r) * DH + c4];
            }
        }

        // ---- un-shifted softmax numerators (base-2, scale pre-folded) ----
#pragma unroll
        for (int i = 0; i < 8; i++) {
            const unsigned mb = (unsigned)(wd[i] >> (tx * 8)) & 0xffu;
            float p[8], psum = 0.f;
#pragma unroll
            for (int j = 0; j < 8; j++) {
                p[j] = (mb & (1u << j)) ? 0.f : fast_ex2(sacc[i][j]);
                psum += p[j];
            }
            lst[i] += psum;   // partial over tx lanes; reduced at end
            float4 pv0 = {p[0], p[1], p[2], p[3]};
            float4 pv1 = {p[4], p[5], p[6], p[7]};
            *(float4*)&Ps[(ty * 8 + i) * 68 + tx * 8]     = pv0;
            *(float4*)&Ps[(ty * 8 + i) * 68 + tx * 8 + 4] = pv1;
        }
        __syncwarp();   // P rows of this ty-group are warp-local

        // ---- O += P V ----
#pragma unroll 2
        for (int k4 = 0; k4 < 16; k4++) {
            float va[4][8];
#pragma unroll
            for (int k = 0; k < 4; k++) {
                float4 v0 = *(const float4*)&Vs[(k4 * 4 + k) * 64 + tx * 8];
                float4 v1 = *(const float4*)&Vs[(k4 * 4 + k) * 64 + tx * 8 + 4];
                va[k][0] = v0.x; va[k][1] = v0.y; va[k][2] = v0.z; va[k][3] = v0.w;
                va[k][4] = v1.x; va[k][5] = v1.y; va[k][6] = v1.z; va[k][7] = v1.w;
            }
#pragma unroll
            for (int i = 0; i < 8; i++) {
                float4 pf = *(const float4*)&Ps[(ty * 8 + i) * 68 + k4 * 4];
#pragma unroll
                for (int c = 0; c < 8; c++)
                    O[i][c] += pf.x * va[0][c] + pf.y * va[1][c]
                             + pf.z * va[2][c] + pf.w * va[3][c];
            }
        }
    }

    // final: reduce l over the 8 tx lanes, normalize, write out
#pragma unroll
    for (int i = 0; i < 8; i++) {
        float l = lst[i];
        l += __shfl_xor_sync(0xffffffffu, l, 1);
        l += __shfl_xor_sync(0xffffffffu, l, 2);
        l += __shfl_xor_sync(0xffffffffu, l, 4);
        const float inv = 1.0f / l;
        const int r = q0 + ty * 8 + i;
        float4 o0 = {O[i][0] * inv, O[i][1] * inv, O[i][2] * inv, O[i][3] * inv};
        float4 o1 = {O[i][4] * inv, O[i][5] * inv, O[i][6] * inv, O[i][7] * inv};
        float* op = &g_O[(size_t)(b * NSEQ + r) * DIMC + h * DH + tx * 8];
        *(float4*)op       = o0;
        *(float4*)(op + 4) = o1;
    }
}

// ============ Projection GEMM (proven body, unchanged) ============
__global__ __launch_bounds__(256, 2) void proj_gemm_kernel(
    const float* __restrict__ W, const float* __restrict__ bias, float* __restrict__ out)
{
    __shared__ float As[16][128];
    __shared__ float Bs[16][128];

    const int tid  = threadIdx.x;
    const int tx   = tid & 15, ty = tid >> 4;
    const int row0 = blockIdx.y * 128;
    const int col0 = blockIdx.x * 128;

    const int ra = tid >> 2;
    const int kc = (tid & 3) << 2;
    const int rb = tid >> 5;
    const int cb = (tid & 31) << 2;

    float acc[2][2][4][4];
#pragma unroll
    for (int ri = 0; ri < 2; ri++)
#pragma unroll
        for (int ci = 0; ci < 2; ci++)
#pragma unroll
            for (int i = 0; i < 4; i++)
#pragma unroll
                for (int j = 0; j < 4; j++) acc[ri][ci][i][j] = 0.f;

    float4 pa0 = *(const float4*)&g_O[(row0 + ra) * DIMC + kc];
    float4 pa1 = *(const float4*)&g_O[(row0 + ra + 64) * DIMC + kc];
    float4 pb0 = *(const float4*)&W[rb * DIMC + col0 + cb];
    float4 pb1 = *(const float4*)&W[(rb + 8) * DIMC + col0 + cb];

    for (int kt = 0; kt < 64; kt++) {
        As[kc + 0][ra] = pa0.x; As[kc + 1][ra] = pa0.y;
        As[kc + 2][ra] = pa0.z; As[kc + 3][ra] = pa0.w;
        As[kc + 0][ra + 64] = pa1.x; As[kc + 1][ra + 64] = pa1.y;
        As[kc + 2][ra + 64] = pa1.z; As[kc + 3][ra + 64] = pa1.w;
        *(float4*)&Bs[rb][cb]     = pb0;
        *(float4*)&Bs[rb + 8][cb] = pb1;
        __syncthreads();
        if (kt < 63) {
            const int k0 = (kt + 1) * 16;
            pa0 = *(const float4*)&g_O[(row0 + ra) * DIMC + k0 + kc];
            pa1 = *(const float4*)&g_O[(row0 + ra + 64) * DIMC + k0 + kc];
            pb0 = *(const float4*)&W[(k0 + rb) * DIMC + col0 + cb];
            pb1 = *(const float4*)&W[(k0 + rb + 8) * DIMC + col0 + cb];
        }
#pragma unroll
        for (int kk = 0; kk < 16; kk++) {
            float4 af0 = *(const float4*)&As[kk][ty * 4];
            float4 af1 = *(const float4*)&As[kk][64 + ty * 4];
            float4 bf0 = *(const float4*)&Bs[kk][tx * 4];
            float4 bf1 = *(const float4*)&Bs[kk][64 + tx * 4];
            float ar[2][4] = {{af0.x, af0.y, af0.z, af0.w}, {af1.x, af1.y, af1.z, af1.w}};
            float br[2][4] = {{bf0.x, bf0.y, bf0.z, bf0.w}, {bf1.x, bf1.y, bf1.z, bf1.w}};
#pragma unroll
            for (int ri = 0; ri < 2; ri++)
#pragma unroll
                for (int ci = 0; ci < 2; ci++)
#pragma unroll
                    for (int i = 0; i < 4; i++)
#pragma unroll
                        for (int j = 0; j < 4; j++)
                            acc[ri][ci][i][j] += ar[ri][i] * br[ci][j];
        }
        __syncthreads();
    }

#pragma unroll
    for (int ri = 0; ri < 2; ri++)
#pragma unroll
        for (int i = 0; i < 4; i++) {
            const int r = row0 + ri * 64 + ty * 4 + i;
#pragma unroll
            for (int ci = 0; ci < 2; ci++) {
                const int c = col0 + ci * 64 + tx * 4;
                float4 bv = *(const float4*)&bias[c];
                float4 v;
                v.x = acc[ri][ci][i][0] + bv.x;
                v.y = acc[ri][ci][i][1] + bv.y;
                v.z = acc[ri][ci][i][2] + bv.z;
                v.w = acc[ri][ci][i][3] + bv.w;
                *(float4*)&out[r * DIMC + c] = v;
            }
        }
}

// ---------------- launch ----------------
extern "C" void kernel_launch(void* const* d_in, const int* in_sizes, int n_in,
                              void* d_out, int out_size)
{
    const float* x     = (const float*)d_in[0];
    const void*  mask  = d_in[1];
    const float* Wqkv  = (const float*)d_in[2];
    const float* bqkv  = (const float*)d_in[3];
    const float* Wproj = (const float*)d_in[4];
    const float* bproj = (const float*)d_in[5];
    float* out = (float*)d_out;

    cudaFuncSetAttribute(flash_attn_kernel,
                         cudaFuncAttributeMaxDynamicSharedMemorySize, ATT_SMEM);

    detect_mask_kernel<<<1, 256>>>((const unsigned*)mask);
    pack_mask_kernel<<<(BSZ * NSEQ) / 8, 256>>>(mask);

    dim3 g1(THREE_C / 128, (BSZ * NSEQ) / 128);   // 24 x 64
    qkv_gemm_kernel<<<g1, 256>>>(x, Wqkv, bqkv);

    dim3 g2(NSEQ / 128, NH, BSZ);                 // 16 x 16 x 4 = 1024 CTAs
    flash_attn_kernel<<<g2, 128, ATT_SMEM>>>();

    dim3 g3(DIMC / 128, (BSZ * NSEQ) / 128);      // 8 x 64
    proj_gemm_kernel<<<g3, 256>>>(Wproj, bproj, out);
}

// round 15
// speedup vs baseline: 1.1487x; 1.0650x over previous
#include <cuda_runtime.h>
#include <cstdint>

#define BSZ  4
#define NSEQ 2048
#define DIMC 1024
#define NH   16
#define DH   64
#define THREE_C 3072
#define NW (NSEQ / 64)     // mask words per row

typedef unsigned long long u64;

// ---------------- scratch (no allocs allowed) ----------------
__device__ float g_Q[BSZ * NH * DH * NSEQ];   // [b,h,d,n]  d-major (pre-scaled log2e/8)
__device__ float g_K[BSZ * NH * DH * NSEQ];   // [b,h,d,n]  d-major
__device__ float g_V[BSZ * NH * NSEQ * DH];   // [b,h,n,d]
__device__ float g_O[BSZ * NSEQ * DIMC];      // [b,n,h*64+d]
__device__ u64   g_Mbits[BSZ * NSEQ * NW];    // bit=1 -> masked
__device__ int   g_mask_is_i32;

__device__ __forceinline__ float fast_ex2(float x) {
    float r; asm("ex2.approx.f32 %0, %1;" : "=f"(r) : "f"(x)); return r;
}

// ---------------- mask dtype probe ----------------
__global__ void detect_mask_kernel(const unsigned* __restrict__ m) {
    __shared__ int bad;
    if (threadIdx.x == 0) bad = 0;
    __syncthreads();
    for (int i = threadIdx.x; i < 4096; i += 256)
        if (m[i] > 1u) bad = 1;
    __syncthreads();
    if (threadIdx.x == 0) g_mask_is_i32 = bad ? 0 : 1;
}

// ---------------- mask bit-pack: one warp per row ----------------
__global__ __launch_bounds__(256) void pack_mask_kernel(const void* __restrict__ mask) {
    const int warp = (blockIdx.x * 256 + threadIdx.x) >> 5;   // row 0..8191
    const int lane = threadIdx.x & 31;
    const int mi32 = g_mask_is_i32;
    if (mi32) {
        const int* m = (const int*)mask + (size_t)warp * NSEQ;
#pragma unroll 4
        for (int w = 0; w < NW; w++) {
            unsigned b0 = __ballot_sync(0xffffffffu, m[w * 64 + lane] != 0);
            unsigned b1 = __ballot_sync(0xffffffffu, m[w * 64 + 32 + lane] != 0);
            if (lane == 0) g_Mbits[warp * NW + w] = (u64)b0 | ((u64)b1 << 32);
        }
    } else {
        const uint8_t* m = (const uint8_t*)mask + (size_t)warp * NSEQ;
#pragma unroll 4
        for (int w = 0; w < NW; w++) {
            unsigned b0 = __ballot_sync(0xffffffffu, m[w * 64 + lane] != 0);
            unsigned b1 = __ballot_sync(0xffffffffu, m[w * 64 + 32 + lane] != 0);
            if (lane == 0) g_Mbits[warp * NW + w] = (u64)b0 | ((u64)b1 << 32);
        }
    }
}

// ============ QKV GEMM (proven body; Q/K d-major; Q scaled by log2e/8) ============
__global__ __launch_bounds__(256, 2) void qkv_gemm_kernel(
    const float* __restrict__ X, const float* __restrict__ W, const float* __restrict__ bias)
{
    __shared__ float As[16][128];
    __shared__ float Bs[16][128];

    const int tid  = threadIdx.x;
    const int tx   = tid & 15, ty = tid >> 4;
    const int row0 = blockIdx.y * 128;
    const int col0 = blockIdx.x * 128;

    const int ra = tid >> 2;
    const int kc = (tid & 3) << 2;
    const int rb = tid >> 5;
    const int cb = (tid & 31) << 2;

    float acc[2][2][4][4];
#pragma unroll
    for (int ri = 0; ri < 2; ri++)
#pragma unroll
        for (int ci = 0; ci < 2; ci++)
#pragma unroll
            for (int i = 0; i < 4; i++)
#pragma unroll
                for (int j = 0; j < 4; j++) acc[ri][ci][i][j] = 0.f;

    float4 pa0 = *(const float4*)&X[(row0 + ra) * DIMC + kc];
    float4 pa1 = *(const float4*)&X[(row0 + ra + 64) * DIMC + kc];
    float4 pb0 = *(const float4*)&W[rb * THREE_C + col0 + cb];
    float4 pb1 = *(const float4*)&W[(rb + 8) * THREE_C + col0 + cb];

    for (int kt = 0; kt < 64; kt++) {
        As[kc + 0][ra] = pa0.x; As[kc + 1][ra] = pa0.y;
        As[kc + 2][ra] = pa0.z; As[kc + 3][ra] = pa0.w;
        As[kc + 0][ra + 64] = pa1.x; As[kc + 1][ra + 64] = pa1.y;
        As[kc + 2][ra + 64] = pa1.z; As[kc + 3][ra + 64] = pa1.w;
        *(float4*)&Bs[rb][cb]     = pb0;
        *(float4*)&Bs[rb + 8][cb] = pb1;
        __syncthreads();
        if (kt < 63) {
            const int k0 = (kt + 1) * 16;
            pa0 = *(const float4*)&X[(row0 + ra) * DIMC + k0 + kc];
            pa1 = *(const float4*)&X[(row0 + ra + 64) * DIMC + k0 + kc];
            pb0 = *(const float4*)&W[(k0 + rb) * THREE_C + col0 + cb];
            pb1 = *(const float4*)&W[(k0 + rb + 8) * THREE_C + col0 + cb];
        }
#pragma unroll
        for (int kk = 0; kk < 16; kk++) {
            float4 af0 = *(const float4*)&As[kk][ty * 4];
            float4 af1 = *(const float4*)&As[kk][64 + ty * 4];
            float4 bf0 = *(const float4*)&Bs[kk][tx * 4];
            float4 bf1 = *(const float4*)&Bs[kk][64 + tx * 4];
            float ar[2][4] = {{af0.x, af0.y, af0.z, af0.w}, {af1.x, af1.y, af1.z, af1.w}};
            float br[2][4] = {{bf0.x, bf0.y, bf0.z, bf0.w}, {bf1.x, bf1.y, bf1.z, bf1.w}};
#pragma unroll
            for (int ri = 0; ri < 2; ri++)
#pragma unroll
                for (int ci = 0; ci < 2; ci++)
#pragma unroll
                    for (int i = 0; i < 4; i++)
#pragma unroll
                        for (int j = 0; j < 4; j++)
                            acc[ri][ci][i][j] += ar[ri][i] * br[ci][j];
        }
        __syncthreads();
    }

    // Q scale folds softmax's log2(e): exp(qk/8) == exp2((log2e/8 * q) . k)
    const float QSCALE = 0.18033688011f;   // 1.4426950408f / 8
#pragma unroll
    for (int ri = 0; ri < 2; ri++)
#pragma unroll
        for (int i = 0; i < 4; i++) {
            const int r  = row0 + ri * 64 + ty * 4 + i;
            const int bb = r >> 11;
            const int n  = r & 2047;
#pragma unroll
            for (int ci = 0; ci < 2; ci++) {
                const int c     = col0 + ci * 64 + tx * 4;
                const int three = c >> 10;
                const int rem   = c & 1023;
                const int h     = rem >> 6;
                const int d     = rem & 63;
                float4 bv = *(const float4*)&bias[c];
                float4 v;
                v.x = acc[ri][ci][i][0] + bv.x;
                v.y = acc[ri][ci][i][1] + bv.y;
                v.z = acc[ri][ci][i][2] + bv.z;
                v.w = acc[ri][ci][i][3] + bv.w;
                if (three == 2) {
                    *(float4*)&g_V[(((bb * NH + h) * NSEQ) + n) * DH + d] = v;
                } else {
                    float sc = 1.0f;
                    float* dst = g_K;
                    if (three == 0) { sc = QSCALE; dst = g_Q; }
                    const int base = ((bb * NH + h) * DH + d) * NSEQ + n;
                    dst[base]            = v.x * sc;
                    dst[base + NSEQ]     = v.y * sc;
                    dst[base + 2 * NSEQ] = v.z * sc;
                    dst[base + 3 * NSEQ] = v.w * sc;
                }
            }
        }
}

// ============ Flash attention: 128 thr, 8x8 micro, NO prefetch, un-shifted exp2 ============
// smem (floats): Qtd[64][128] @0, Kt[64][64] @8192, Vs[64][64] @12288, Ps[128][68] @16384
#define ATT_SMEM ((8192 + 4096 + 4096 + 128 * 68) * 4)   // 100352 B

__global__ __launch_bounds__(128, 2) void flash_attn_kernel()
{
    extern __shared__ float smf[];
    float* Qtd = smf;            // [64 d][128 r]
    float* Kt  = smf + 8192;     // [64 d][64 k]
    float* Vs  = smf + 12288;    // [64 k][64 c]
    float* Ps  = smf + 16384;    // [128 r][68]

    const int b   = blockIdx.z;
    const int h   = blockIdx.y;
    const int q0  = blockIdx.x * 128;
    const int tid = threadIdx.x;
    const int tx  = tid & 7;     // key/col octet
    const int ty  = tid >> 3;    // row group (0..15), 8 rows each

    const int bh = b * NH + h;
    const float* __restrict__ Qg = g_Q + (size_t)bh * DH * NSEQ;
    const float* __restrict__ Kg = g_K + (size_t)bh * DH * NSEQ;
    const float* __restrict__ Vg = g_V + (size_t)bh * NSEQ * DH;
    const u64*   __restrict__ Mb = g_Mbits + ((size_t)b * NSEQ + q0) * NW;

    // Q tile load (coalesced, d-major, no transpose): 2048 float4 / 128 thr
#pragma unroll
    for (int it = 0; it < 16; it++) {
        const int idx = it * 128 + tid;
        const int d   = idx >> 5;
        const int r4  = (idx & 31) << 2;
        *(float4*)&Qtd[d * 128 + r4] = *(const float4*)&Qg[d * NSEQ + q0 + r4];
    }

    float lst[8], O[8][8];
#pragma unroll
    for (int i = 0; i < 8; i++) {
        lst[i] = 0.f;
#pragma unroll
        for (int c = 0; c < 8; c++) O[i][c] = 0.f;
    }

    for (int t = 0; t < NW; t++) {
        __syncthreads();   // previous tile's smem reads complete
        // load K/V tile straight to smem (coalesced): 1024 float4 / 128 thr
#pragma unroll
        for (int it = 0; it < 8; it++) {
            const int idx = it * 128 + tid;
            const int r   = idx >> 4;
            const int c4  = (idx & 15) << 2;
            *(float4*)&Kt[r * 64 + c4] = *(const float4*)&Kg[r * NSEQ + t * 64 + c4];
            *(float4*)&Vs[r * 64 + c4] = *(const float4*)&Vg[(t * 64 + r) * DH + c4];
        }
        // mask words for this thread's 8 rows
        u64 wd[8];
#pragma unroll
        for (int i = 0; i < 8; i++)
            wd[i] = Mb[(ty * 8 + i) * NW + t];
        __syncthreads();   // tile ready (also covers Qtd on t=0)

        // ---- S = Q K^T ----
        float sacc[8][8];
#pragma unroll
        for (int i = 0; i < 8; i++)
#pragma unroll
            for (int j = 0; j < 8; j++) sacc[i][j] = 0.f;

#pragma unroll 2
        for (int d = 0; d < 64; d++) {
            float4 qa0 = *(const float4*)&Qtd[d * 128 + ty * 8];
            float4 qa1 = *(const float4*)&Qtd[d * 128 + ty * 8 + 4];
            float4 kb0 = *(const float4*)&Kt[d * 64 + tx * 8];
            float4 kb1 = *(const float4*)&Kt[d * 64 + tx * 8 + 4];
            float qa[8] = {qa0.x, qa0.y, qa0.z, qa0.w, qa1.x, qa1.y, qa1.z, qa1.w};
            float kb[8] = {kb0.x, kb0.y, kb0.z, kb0.w, kb1.x, kb1.y, kb1.z, kb1.w};
#pragma unroll
            for (int i = 0; i < 8; i++)
#pragma unroll
                for (int j = 0; j < 8; j++)
                    sacc[i][j] += qa[i] * kb[j];
        }

        // ---- un-shifted softmax numerators (base-2, scale pre-folded) ----
#pragma unroll
        for (int i = 0; i < 8; i++) {
            const unsigned mb = (unsigned)(wd[i] >> (tx * 8)) & 0xffu;
            float p[8], psum = 0.f;
#pragma unroll
            for (int j = 0; j < 8; j++) {
                p[j] = (mb & (1u << j)) ? 0.f : fast_ex2(sacc[i][j]);
                psum += p[j];
            }
            lst[i] += psum;   // partial over tx lanes; reduced at end
            float4 pv0 = {p[0], p[1], p[2], p[3]};
            float4 pv1 = {p[4], p[5], p[6], p[7]};
            *(float4*)&Ps[(ty * 8 + i) * 68 + tx * 8]     = pv0;
            *(float4*)&Ps[(ty * 8 + i) * 68 + tx * 8 + 4] = pv1;
        }
        __syncwarp();   // P rows of this ty-group are warp-local

        // ---- O += P V ----
#pragma unroll 2
        for (int k4 = 0; k4 < 16; k4++) {
            float va[4][8];
#pragma unroll
            for (int k = 0; k < 4; k++) {
                float4 v0 = *(const float4*)&Vs[(k4 * 4 + k) * 64 + tx * 8];
                float4 v1 = *(const float4*)&Vs[(k4 * 4 + k) * 64 + tx * 8 + 4];
                va[k][0] = v0.x; va[k][1] = v0.y; va[k][2] = v0.z; va[k][3] = v0.w;
                va[k][4] = v1.x; va[k][5] = v1.y; va[k][6] = v1.z; va[k][7] = v1.w;
            }
#pragma unroll
            for (int i = 0; i < 8; i++) {
                float4 pf = *(const float4*)&Ps[(ty * 8 + i) * 68 + k4 * 4];
#pragma unroll
                for (int c = 0; c < 8; c++)
                    O[i][c] += pf.x * va[0][c] + pf.y * va[1][c]
                             + pf.z * va[2][c] + pf.w * va[3][c];
            }
        }
    }

    // final: reduce l over the 8 tx lanes, normalize, write out
#pragma unroll
    for (int i = 0; i < 8; i++) {
        float l = lst[i];
        l += __shfl_xor_sync(0xffffffffu, l, 1);
        l += __shfl_xor_sync(0xffffffffu, l, 2);
        l += __shfl_xor_sync(0xffffffffu, l, 4);
        const float inv = 1.0f / l;
        const int r = q0 + ty * 8 + i;
        float4 o0 = {O[i][0] * inv, O[i][1] * inv, O[i][2] * inv, O[i][3] * inv};
        float4 o1 = {O[i][4] * inv, O[i][5] * inv, O[i][6] * inv, O[i][7] * inv};
        float* op = &g_O[(size_t)(b * NSEQ + r) * DIMC + h * DH + tx * 8];
        *(float4*)op       = o0;
        *(float4*)(op + 4) = o1;
    }
}

// ============ Projection GEMM (proven body, unchanged) ============
__global__ __launch_bounds__(256, 2) void proj_gemm_kernel(
    const float* __restrict__ W, const float* __restrict__ bias, float* __restrict__ out)
{
    __shared__ float As[16][128];
    __shared__ float Bs[16][128];

    const int tid  = threadIdx.x;
    const int tx   = tid & 15, ty = tid >> 4;
    const int row0 = blockIdx.y * 128;
    const int col0 = blockIdx.x * 128;

    const int ra = tid >> 2;
    const int kc = (tid & 3) << 2;
    const int rb = tid >> 5;
    const int cb = (tid & 31) << 2;

    float acc[2][2][4][4];
#pragma unroll
    for (int ri = 0; ri < 2; ri++)
#pragma unroll
        for (int ci = 0; ci < 2; ci++)
#pragma unroll
            for (int i = 0; i < 4; i++)
#pragma unroll
                for (int j = 0; j < 4; j++) acc[ri][ci][i][j] = 0.f;

    float4 pa0 = *(const float4*)&g_O[(row0 + ra) * DIMC + kc];
    float4 pa1 = *(const float4*)&g_O[(row0 + ra + 64) * DIMC + kc];
    float4 pb0 = *(const float4*)&W[rb * DIMC + col0 + cb];
    float4 pb1 = *(const float4*)&W[(rb + 8) * DIMC + col0 + cb];

    for (int kt = 0; kt < 64; kt++) {
        As[kc + 0][ra] = pa0.x; As[kc + 1][ra] = pa0.y;
        As[kc + 2][ra] = pa0.z; As[kc + 3][ra] = pa0.w;
        As[kc + 0][ra + 64] = pa1.x; As[kc + 1][ra + 64] = pa1.y;
        As[kc + 2][ra + 64] = pa1.z; As[kc + 3][ra + 64] = pa1.w;
        *(float4*)&Bs[rb][cb]     = pb0;
        *(float4*)&Bs[rb + 8][cb] = pb1;
        __syncthreads();
        if (kt < 63) {
            const int k0 = (kt + 1) * 16;
            pa0 = *(const float4*)&g_O[(row0 + ra) * DIMC + k0 + kc];
            pa1 = *(const float4*)&g_O[(row0 + ra + 64) * DIMC + k0 + kc];
            pb0 = *(const float4*)&W[(k0 + rb) * DIMC + col0 + cb];
            pb1 = *(const float4*)&W[(k0 + rb + 8) * DIMC + col0 + cb];
        }
#pragma unroll
        for (int kk = 0; kk < 16; kk++) {
            float4 af0 = *(const float4*)&As[kk][ty * 4];
            float4 af1 = *(const float4*)&As[kk][64 + ty * 4];
            float4 bf0 = *(const float4*)&Bs[kk][tx * 4];
            float4 bf1 = *(const float4*)&Bs[kk][64 + tx * 4];
            float ar[2][4] = {{af0.x, af0.y, af0.z, af0.w}, {af1.x, af1.y, af1.z, af1.w}};
            float br[2][4] = {{bf0.x, bf0.y, bf0.z, bf0.w}, {bf1.x, bf1.y, bf1.z, bf1.w}};
#pragma unroll
            for (int ri = 0; ri < 2; ri++)
#pragma unroll
                for (int ci = 0; ci < 2; ci++)
#pragma unroll
                    for (int i = 0; i < 4; i++)
#pragma unroll
                        for (int j = 0; j < 4; j++)
                            acc[ri][ci][i][j] += ar[ri][i] * br[ci][j];
        }
        __syncthreads();
    }

#pragma unroll
    for (int ri = 0; ri < 2; ri++)
#pragma unroll
        for (int i = 0; i < 4; i++) {
            const int r = row0 + ri * 64 + ty * 4 + i;
#pragma unroll
            for (int ci = 0; ci < 2; ci++) {
                const int c = col0 + ci * 64 + tx * 4;
                float4 bv = *(const float4*)&bias[c];
                float4 v;
                v.x = acc[ri][ci][i][0] + bv.x;
                v.y = acc[ri][ci][i][1] + bv.y;
                v.z = acc[ri][ci][i][2] + bv.z;
                v.w = acc[ri][ci][i][3] + bv.w;
                *(float4*)&out[r * DIMC + c] = v;
            }
        }
}

// ---------------- launch ----------------
extern "C" void kernel_launch(void* const* d_in, const int* in_sizes, int n_in,
                              void* d_out, int out_size)
{
    const float* x     = (const float*)d_in[0];
    const void*  mask  = d_in[1];
    const float* Wqkv  = (const float*)d_in[2];
    const float* bqkv  = (const float*)d_in[3];
    const float* Wproj = (const float*)d_in[4];
    const float* bproj = (const float*)d_in[5];
    float* out = (float*)d_out;

    cudaFuncSetAttribute(flash_attn_kernel,
                         cudaFuncAttributeMaxDynamicSharedMemorySize, ATT_SMEM);

    detect_mask_kernel<<<1, 256>>>((const unsigned*)mask);
    pack_mask_kernel<<<(BSZ * NSEQ) / 8, 256>>>(mask);

    dim3 g1(THREE_C / 128, (BSZ * NSEQ) / 128);   // 24 x 64
    qkv_gemm_kernel<<<g1, 256>>>(x, Wqkv, bqkv);

    dim3 g2(NSEQ / 128, NH, BSZ);                 // 16 x 16 x 4 = 1024 CTAs
    flash_attn_kernel<<<g2, 128, ATT_SMEM>>>();

    dim3 g3(DIMC / 128, (BSZ * NSEQ) / 128);      // 8 x 64
    proj_gemm_kernel<<<g3, 256>>>(Wproj, bproj, out);
}